// round 12
// baseline (speedup 1.0000x reference)
#include <cuda_runtime.h>
#include <cuda_bf16.h>

// Circular self-convolution via packed real FFT (two real rows per complex
// transform). R12: 96 CTAs x 256 threads, TWO independent transforms per CTA
// interleaved in-thread:
//  - each thread runs the same butterfly for transform A and transform B
//    (two independent dependency chains -> 2x ILP, hides LDS latency)
//  - twiddle loads, index math, sincospif, and barriers shared across both
//  - 96 CTAs < 148 SMs: every active SM has exactly one CTA (kills the
//    double-loaded-SM tail that set R11's wall)
// Barrier scheme identical to R11 (syncwarp for warp-local stages L=64,16,4;
// syncthreads at global boundaries). Arithmetic per transform unchanged.

#define N_CONV 1024
#define THREADS 256

#define P2(i) ((i) + ((i) >> 4))

__device__ __forceinline__ int rev4(int p) {
    return ((p & 3) << 8) | (((p >> 2) & 3) << 6) | (((p >> 4) & 3) << 4)
         | (((p >> 6) & 3) << 2) | ((p >> 8) & 3);
}

// Complex helpers on float2.
__device__ __forceinline__ float2 cadd(float2 a, float2 b) { return make_float2(a.x + b.x, a.y + b.y); }
__device__ __forceinline__ float2 csub(float2 a, float2 b) { return make_float2(a.x - b.x, a.y - b.y); }
__device__ __forceinline__ float2 cmul(float2 a, float2 w) {
    return make_float2(a.x * w.x - a.y * w.y, a.x * w.y + a.y * w.x);
}
__device__ __forceinline__ float2 cmulc(float2 a, float2 w) {   // a * conj(w)
    return make_float2(a.x * w.x + a.y * w.y, a.y * w.x - a.x * w.y);
}
__device__ __forceinline__ float2 submuli(float2 a, float2 b) {  // a - i*b
    return make_float2(a.x + b.y, a.y - b.x);
}
__device__ __forceinline__ float2 addmuli(float2 a, float2 b) {  // a + i*b
    return make_float2(a.x - b.y, a.y + b.x);
}

// Forward DIF radix-4 stage applied to both transforms, in-place.
template<int L>
__device__ __forceinline__ void fwd_stage2(float2* X0, float2* X1,
                                           const float2* W, int t)
{
    const int q    = L >> 2;
    const int blk  = t / q;
    const int pos  = t % q;
    const int base = blk * L + pos;
    const int w1   = pos * (N_CONV / L);

    const int i0 = P2(base), i1 = P2(base + q), i2 = P2(base + 2*q), i3 = P2(base + 3*q);

    const float2 w1v = W[P2(w1)];
    const float2 w2v = W[P2(2*w1)];
    const float2 w3v = W[P2(3*w1)];

    #pragma unroll
    for (int s = 0; s < 2; ++s) {
        float2* X = s ? X1 : X0;
        const float2 a0 = X[i0], a1 = X[i1], a2 = X[i2], a3 = X[i3];

        const float2 t0 = cadd(a0, a2);
        const float2 t1 = csub(a0, a2);
        const float2 t2 = cadd(a1, a3);
        const float2 t3 = csub(a1, a3);

        X[i0] = cadd(t0, t2);
        X[i1] = cmul(submuli(t1, t3), w1v);
        X[i2] = cmul(csub(t0, t2), w2v);
        X[i3] = cmul(addmuli(t1, t3), w3v);
    }
}

// Inverse stage (un-twiddle by conj(W), inverse butterfly), both transforms.
template<int L>
__device__ __forceinline__ void inv_stage2(float2* X0, float2* X1,
                                           const float2* W, int t)
{
    const int q    = L >> 2;
    const int blk  = t / q;
    const int pos  = t % q;
    const int base = blk * L + pos;
    const int w1   = pos * (N_CONV / L);

    const int i0 = P2(base), i1 = P2(base + q), i2 = P2(base + 2*q), i3 = P2(base + 3*q);

    const float2 w1v = W[P2(w1)];
    const float2 w2v = W[P2(2*w1)];
    const float2 w3v = W[P2(3*w1)];

    #pragma unroll
    for (int s = 0; s < 2; ++s) {
        float2* X = s ? X1 : X0;
        const float2 a0 = X[i0];
        const float2 a1 = cmulc(X[i1], w1v);
        const float2 a2 = cmulc(X[i2], w2v);
        const float2 a3 = cmulc(X[i3], w3v);

        const float2 t0 = cadd(a0, a2);
        const float2 t1 = csub(a0, a2);
        const float2 t2 = cadd(a1, a3);
        const float2 t3 = csub(a1, a3);

        X[i0] = cadd(t0, t2);
        X[i1] = addmuli(t1, t3);
        X[i2] = csub(t0, t2);
        X[i3] = submuli(t1, t3);
    }
}

__global__ __launch_bounds__(THREADS, 1)
void mcf_fft7_kernel(const float* __restrict__ x1,
                     const float* __restrict__ x2,
                     const float* __restrict__ x3,
                     float* __restrict__ out)
{
    __shared__ __align__(16) float2 X0[1088];
    __shared__ __align__(16) float2 X1[1088];
    __shared__ __align__(16) float2 W[1088];

    const int bx = blockIdx.x;             // 0..95: two row pairs
    // Rows 4bx..4bx+3, all within one array (128 rows/array, 4 | 128).
    const int arr  = bx >> 5;
    const int lrow = (bx & 31) << 2;

    const float* xp  = (arr == 0) ? x1 : ((arr == 1) ? x2 : x3);
    const float* xa0 = xp + (size_t)lrow * N_CONV;
    const float* xb0 = xa0 + N_CONV;
    const float* xa1 = xb0 + N_CONV;
    const float* xb1 = xa1 + N_CONV;

    const int t = threadIdx.x;

    // Prologue: float4 loads for both transforms, one sincospif.
    {
        const float4 va0 = ((const float4*)xa0)[t];
        const float4 vb0 = ((const float4*)xb0)[t];
        const float4 va1 = ((const float4*)xa1)[t];
        const float4 vb1 = ((const float4*)xb1)[t];

        float sn, cs;
        sincospif((float)t * (1.0f / 512.0f), &sn, &cs);
        W[P2(t)]       = make_float2(cs, -sn);
        W[P2(t + 256)] = make_float2(-sn, -cs);
        W[P2(t + 512)] = make_float2(-cs, sn);
        W[P2(t + 768)] = make_float2(sn, cs);

        const int b = 4 * t;
        X0[P2(b)]     = make_float2(va0.x, vb0.x);
        X0[P2(b + 1)] = make_float2(va0.y, vb0.y);
        X0[P2(b + 2)] = make_float2(va0.z, vb0.z);
        X0[P2(b + 3)] = make_float2(va0.w, vb0.w);
        X1[P2(b)]     = make_float2(va1.x, vb1.x);
        X1[P2(b + 1)] = make_float2(va1.y, vb1.y);
        X1[P2(b + 2)] = make_float2(va1.z, vb1.z);
        X1[P2(b + 3)] = make_float2(va1.w, vb1.w);
    }
    __syncthreads();

    // Global forward stages.
    fwd_stage2<1024>(X0, X1, W, t); __syncthreads();
    fwd_stage2< 256>(X0, X1, W, t); __syncthreads();

    // Warp-local forward stages.
    fwd_stage2<  64>(X0, X1, W, t); __syncwarp();
    fwd_stage2<  16>(X0, X1, W, t); __syncwarp();

    // Fused fwd L=4 (identity twiddles): keep Z in registers, publish.
    float2 Z0[4], Z1[4];
    {
        const int b = 4 * t;
        const int i0 = P2(b), i1 = P2(b + 1), i2 = P2(b + 2), i3 = P2(b + 3);
        #pragma unroll
        for (int s = 0; s < 2; ++s) {
            float2* X = s ? X1 : X0;
            float2* Z = s ? Z1 : Z0;
            const float2 a0 = X[i0], a1 = X[i1], a2 = X[i2], a3 = X[i3];
            const float2 t0 = cadd(a0, a2);
            const float2 t1 = csub(a0, a2);
            const float2 t2 = cadd(a1, a3);
            const float2 t3 = csub(a1, a3);
            Z[0] = cadd(t0, t2);
            Z[1] = submuli(t1, t3);
            Z[2] = csub(t0, t2);
            Z[3] = addmuli(t1, t3);
            X[i0] = Z[0]; X[i1] = Z[1]; X[i2] = Z[2]; X[i3] = Z[3];
        }
    }
    __syncthreads();   // middle reads global mirror positions

    // Middle: conj-symmetry unpack + square + repack for both transforms.
    float2 Y0[4], Y1[4];
    {
        #pragma unroll
        for (int j = 0; j < 4; ++j) {
            const int p  = 4 * t + j;
            const int k  = rev4(p);
            const int pm = P2(rev4((N_CONV - k) & (N_CONV - 1)));

            #pragma unroll
            for (int s = 0; s < 2; ++s) {
                const float2 Zp = s ? Z1[j] : Z0[j];
                const float2 M  = s ? X1[pm] : X0[pm];

                const float Ar = 0.5f * (Zp.x + M.x), Ai = 0.5f * (Zp.y - M.y);
                const float Br = 0.5f * (Zp.y + M.y), Bi = 0.5f * (M.x - Zp.x);

                const float Yar = Ar*Ar - Ai*Ai, Yai = 2.0f*Ar*Ai;
                const float Ybr = Br*Br - Bi*Bi, Ybi = 2.0f*Br*Bi;
                float2& Yd = s ? Y1[j] : Y0[j];
                Yd = make_float2(Yar - Ybi, Yai + Ybr);
            }
        }
    }
    __syncthreads();   // mirror reads complete before in-place writes
    {
        const int b = 4 * t;
        const int i0 = P2(b), i1 = P2(b + 1), i2 = P2(b + 2), i3 = P2(b + 3);
        #pragma unroll
        for (int s = 0; s < 2; ++s) {
            float2* X = s ? X1 : X0;
            float2* Y = s ? Y1 : Y0;
            const float2 t0 = cadd(Y[0], Y[2]);
            const float2 t1 = csub(Y[0], Y[2]);
            const float2 t2 = cadd(Y[1], Y[3]);
            const float2 t3 = csub(Y[1], Y[3]);
            X[i0] = cadd(t0, t2);
            X[i1] = addmuli(t1, t3);
            X[i2] = csub(t0, t2);
            X[i3] = submuli(t1, t3);
        }
    }
    __syncwarp();

    // Warp-local inverse stages.
    inv_stage2<  16>(X0, X1, W, t); __syncwarp();
    inv_stage2<  64>(X0, X1, W, t); __syncthreads();

    inv_stage2< 256>(X0, X1, W, t); __syncthreads();

    // Final inverse stage L=1024: write all four rows to gmem.
    {
        const int i0 = P2(t), i1 = P2(t + 256), i2 = P2(t + 512), i3 = P2(t + 768);
        const float2 w1v = W[P2(t)];
        const float2 w2v = W[P2(2*t)];
        const float2 w3v = W[P2(3*t)];
        const float inv_n = 1.0f / 1024.0f;

        float* obase = out + (size_t)arr * 128 * N_CONV + (size_t)lrow * N_CONV;

        #pragma unroll
        for (int s = 0; s < 2; ++s) {
            float2* X = s ? X1 : X0;
            const float2 a0 = X[i0];
            const float2 a1 = cmulc(X[i1], w1v);
            const float2 a2 = cmulc(X[i2], w2v);
            const float2 a3 = cmulc(X[i3], w3v);

            const float2 t0 = cadd(a0, a2);
            const float2 t1 = csub(a0, a2);
            const float2 t2 = cadd(a1, a3);
            const float2 t3 = csub(a1, a3);

            const float2 o0 = cadd(t0, t2);
            const float2 o1 = addmuli(t1, t3);
            const float2 o2 = csub(t0, t2);
            const float2 o3 = submuli(t1, t3);

            float* orowA = obase + (size_t)(2 * s) * N_CONV;
            float* orowB = orowA + N_CONV;

            orowA[t]       = o0.x * inv_n;  orowB[t]       = o0.y * inv_n;
            orowA[t + 256] = o1.x * inv_n;  orowB[t + 256] = o1.y * inv_n;
            orowA[t + 512] = o2.x * inv_n;  orowB[t + 512] = o2.y * inv_n;
            orowA[t + 768] = o3.x * inv_n;  orowB[t + 768] = o3.y * inv_n;
        }
    }
}

extern "C" void kernel_launch(void* const* d_in, const int* in_sizes, int n_in,
                              void* d_out, int out_size)
{
    const float* x1 = (const float*)d_in[0];
    const float* x2 = (const float*)d_in[1];
    const float* x3 = (const float*)d_in[2];
    float* out = (float*)d_out;

    mcf_fft7_kernel<<<96, THREADS>>>(x1, x2, x3, out);
}

// round 13
// speedup vs baseline: 1.0547x; 1.0547x over previous
#include <cuda_runtime.h>
#include <cuda_bf16.h>

// Circular self-convolution via half-length real FFT. One ROW per CTA:
//   u[m] = x[2m] + i*x[2m+1]  (m=0..511)  -> FFT-512 (DIF, digit-reversed)
//   rfft combine + square + inverse-pack  (middle, fully pairwise-local)
//   inverse FFT-512 (exact unwind)        -> y[2m] = Re v[m], y[2m+1] = Im v[m]
// 384 CTAs x 128 threads: finer work units fix the per-SM wall (R11/R12 were
// pinned at 2 FFT-1024-equivalents on loaded SMs; now 3 half-size jobs = 1.5,
// with 3 independent barrier domains per SM overlapping phase latencies).
//
// FFT-512 = radix-4 stages L=512,128,32,8 + radix-2 L=2 (thread-local).
// Twiddles T[j] = W1024^j (full 1024 table; FFT-512 uses T[2j]).
// Middle for pair (k,512-k): E=(Uk+conj(Um))/2, O=-i(Uk-conj(Um))/2,
//   Xp=E+w O, Xm=E-w O (w=T[k]); S=(Xp^2+Xm^2)/2, Dm=(Xp^2-Xm^2)/2;
//   V[k]=S+i*conj(w)*Dm, V[512-k]=conj(S)+i*w*conj(Dm).
// Verified analytically on constant and delta inputs.

#define N_CONV 1024
#define HF 512
#define THREADS 128

#define P2(i) ((i) + ((i) >> 4))

// Inverse of the FFT-512 output permutation: position of frequency k.
// Stage order r4(512),r4(128),r4(32),r4(8),r2(2):
//   k = s1 + 4 s2 + 16 s3 + 64 s4 + 256 c ;  p = 128 s1 + 32 s2 + 8 s3 + 2 s4 + c
__device__ __forceinline__ int rev_inv(int k) {
    return ((k & 3) << 7) | (((k >> 2) & 3) << 5) | (((k >> 4) & 3) << 3)
         | (((k >> 6) & 3) << 1) | ((k >> 8) & 1);
}

__device__ __forceinline__ float2 cadd(float2 a, float2 b) { return make_float2(a.x + b.x, a.y + b.y); }
__device__ __forceinline__ float2 csub(float2 a, float2 b) { return make_float2(a.x - b.x, a.y - b.y); }
__device__ __forceinline__ float2 cmul(float2 a, float2 w) {
    return make_float2(a.x * w.x - a.y * w.y, a.x * w.y + a.y * w.x);
}
__device__ __forceinline__ float2 cmulc(float2 a, float2 w) {   // a * conj(w)
    return make_float2(a.x * w.x + a.y * w.y, a.y * w.x - a.x * w.y);
}
__device__ __forceinline__ float2 submuli(float2 a, float2 b) {  // a - i*b
    return make_float2(a.x + b.y, a.y - b.x);
}
__device__ __forceinline__ float2 addmuli(float2 a, float2 b) {  // a + i*b
    return make_float2(a.x - b.y, a.y + b.x);
}
__device__ __forceinline__ float2 csq(float2 a) {
    return make_float2(a.x * a.x - a.y * a.y, 2.0f * a.x * a.y);
}

// Forward DIF radix-4 stage for FFT-512 (twiddles = T[2*j]).
template<int L>
__device__ __forceinline__ void fwd_stage(float2* X, const float2* T, int t)
{
    const int q    = L >> 2;
    const int tws2 = 2 * (HF / L);       // factor 2: T holds W1024 powers
    const int blk  = t / q;
    const int pos  = t % q;
    const int base = blk * L + pos;
    const int j1   = pos * tws2;

    const float2 a0 = X[P2(base)];
    const float2 a1 = X[P2(base + q)];
    const float2 a2 = X[P2(base + 2*q)];
    const float2 a3 = X[P2(base + 3*q)];

    const float2 t0 = cadd(a0, a2);
    const float2 t1 = csub(a0, a2);
    const float2 t2 = cadd(a1, a3);
    const float2 t3 = csub(a1, a3);

    X[P2(base)]       = cadd(t0, t2);
    X[P2(base + q)]   = cmul(submuli(t1, t3), T[P2(j1)]);
    X[P2(base + 2*q)] = cmul(csub(t0, t2),    T[P2(2*j1)]);
    X[P2(base + 3*q)] = cmul(addmuli(t1, t3), T[P2(3*j1)]);
}

// Inverse radix-4 stage (un-twiddle by conj, inverse butterfly).
template<int L>
__device__ __forceinline__ void inv_stage(float2* X, const float2* T, int t)
{
    const int q    = L >> 2;
    const int tws2 = 2 * (HF / L);
    const int blk  = t / q;
    const int pos  = t % q;
    const int base = blk * L + pos;
    const int j1   = pos * tws2;

    const float2 a0 = X[P2(base)];
    const float2 a1 = cmulc(X[P2(base + q)],   T[P2(j1)]);
    const float2 a2 = cmulc(X[P2(base + 2*q)], T[P2(2*j1)]);
    const float2 a3 = cmulc(X[P2(base + 3*q)], T[P2(3*j1)]);

    const float2 t0 = cadd(a0, a2);
    const float2 t1 = csub(a0, a2);
    const float2 t2 = cadd(a1, a3);
    const float2 t3 = csub(a1, a3);

    X[P2(base)]       = cadd(t0, t2);
    X[P2(base + q)]   = addmuli(t1, t3);
    X[P2(base + 2*q)] = csub(t0, t2);
    X[P2(base + 3*q)] = submuli(t1, t3);
}

// Middle unit for pair (k, 512-k): reads/writes only its own 2 positions.
__device__ __forceinline__ void middle_unit(float2* X, const float2* T, int k)
{
    const int pk = rev_inv(k);
    const int pm = rev_inv((HF - k) & (HF - 1));

    const float2 Uk = X[P2(pk)];
    const float2 Um = X[P2(pm)];

    const float2 E = make_float2(0.5f * (Uk.x + Um.x), 0.5f * (Uk.y - Um.y));
    const float2 D = make_float2(Uk.x - Um.x, Uk.y + Um.y);
    const float2 O = make_float2(0.5f * D.y, -0.5f * D.x);   // -i*D/2

    const float2 w  = T[P2(k)];                // W1024^k
    const float2 wO = cmul(O, w);
    const float2 Xp = cadd(E, wO);             // X[k]
    const float2 Xm = csub(E, wO);             // X[k+512]

    const float2 P = csq(Xp);
    const float2 M = csq(Xm);
    const float2 S  = make_float2(0.5f * (P.x + M.x), 0.5f * (P.y + M.y));
    const float2 Dm = make_float2(0.5f * (P.x - M.x), 0.5f * (P.y - M.y));

    const float2 r = cmulc(Dm, w);             // conj(w)*Dm
    const float2 Vk = make_float2(S.x - r.y, S.y + r.x);        // S + i*r

    const float2 q2 = cmul(make_float2(Dm.x, -Dm.y), w);        // w*conj(Dm)
    const float2 Vm = make_float2(S.x - q2.y, -S.y + q2.x);     // conj(S)+i*q2

    X[P2(pk)] = Vk;
    X[P2(pm)] = Vm;
}

__global__ __launch_bounds__(THREADS, 3)
void mcf_rfft_kernel(const float* __restrict__ x1,
                     const float* __restrict__ x2,
                     const float* __restrict__ x3,
                     float* __restrict__ out)
{
    __shared__ __align__(16) float2 X[546];     // 512 + padding
    __shared__ __align__(16) float2 T[1088];    // 1024 + padding

    const int bx  = blockIdx.x;                 // 0..383: one row
    const int arr = bx >> 7;
    const int row = bx & 127;

    const float* xp = (arr == 0) ? x1 : ((arr == 1) ? x2 : x3);
    const float* xr = xp + (size_t)row * N_CONV;

    const int t = threadIdx.x;

    // Prologue: pack u[m] = x[2m] + i*x[2m+1]; build twiddle table T.
    {
        const float4 v0 = ((const float4*)xr)[2 * t];
        const float4 v1 = ((const float4*)xr)[2 * t + 1];

        // T[j] = W1024^j = cos(pi j/512) - i sin(pi j/512).
        // Quarter symmetries: T[j+256] = -i T[j]; T[j+512] = -T[j];
        // T[j+768] = i T[j].
        #pragma unroll
        for (int m = 0; m < 2; ++m) {
            const int j = t + 128 * m;
            float sn, cs;
            sincospif((float)j * (1.0f / 512.0f), &sn, &cs);
            T[P2(j)]       = make_float2(cs, -sn);
            T[P2(j + 256)] = make_float2(-sn, -cs);
            T[P2(j + 512)] = make_float2(-cs, sn);
            T[P2(j + 768)] = make_float2(sn, cs);
        }

        const int b = 4 * t;
        X[P2(b)]     = make_float2(v0.x, v0.y);
        X[P2(b + 1)] = make_float2(v0.z, v0.w);
        X[P2(b + 2)] = make_float2(v1.x, v1.y);
        X[P2(b + 3)] = make_float2(v1.z, v1.w);
    }
    __syncthreads();

    // Forward FFT-512.
    fwd_stage<512>(X, T, t); __syncthreads();
    fwd_stage<128>(X, T, t); __syncwarp();
    fwd_stage< 32>(X, T, t); __syncwarp();
    fwd_stage<  8>(X, T, t); __syncwarp();

    // Radix-2 stage L=2 (thread-local, no twiddles).
    {
        const int b = 4 * t;
        const float2 a0 = X[P2(b)],     a1 = X[P2(b + 1)];
        const float2 a2 = X[P2(b + 2)], a3 = X[P2(b + 3)];
        X[P2(b)]     = cadd(a0, a1);
        X[P2(b + 1)] = csub(a0, a1);
        X[P2(b + 2)] = cadd(a2, a3);
        X[P2(b + 3)] = csub(a2, a3);
    }
    __syncthreads();   // middle reads scattered global positions

    // Middle: rfft combine + square + inverse-pack, pairwise in-place.
    middle_unit(X, T, 2 * t);
    middle_unit(X, T, 2 * t + 1);
    if (t == 0) middle_unit(X, T, 256);   // self-pair at position rev_inv(256)
    __syncthreads();

    // Inverse radix-2 stage (thread-local).
    {
        const int b = 4 * t;
        const float2 o0 = X[P2(b)],     o1 = X[P2(b + 1)];
        const float2 o2 = X[P2(b + 2)], o3 = X[P2(b + 3)];
        X[P2(b)]     = cadd(o0, o1);
        X[P2(b + 1)] = csub(o0, o1);
        X[P2(b + 2)] = cadd(o2, o3);
        X[P2(b + 3)] = csub(o2, o3);
    }
    __syncwarp();

    inv_stage<  8>(X, T, t); __syncwarp();
    inv_stage< 32>(X, T, t); __syncwarp();
    inv_stage<128>(X, T, t); __syncthreads();

    // Final inverse stage L=512 fused with epilogue de-pack to gmem.
    {
        const float2 a0 = X[P2(t)];
        const float2 a1 = cmulc(X[P2(t + 128)], T[P2(2*t)]);
        const float2 a2 = cmulc(X[P2(t + 256)], T[P2(4*t)]);
        const float2 a3 = cmulc(X[P2(t + 384)], T[P2(6*t)]);

        const float2 t0 = cadd(a0, a2);
        const float2 t1 = csub(a0, a2);
        const float2 t2 = cadd(a1, a3);
        const float2 t3 = csub(a1, a3);

        const float2 v0 = cadd(t0, t2);        // v[t]
        const float2 v1 = addmuli(t1, t3);     // v[t+128]
        const float2 v2 = csub(t0, t2);        // v[t+256]
        const float2 v3 = submuli(t1, t3);     // v[t+384]

        const float inv_n = 1.0f / 512.0f;
        float2* orow = (float2*)(out + (size_t)arr * 128 * N_CONV
                                     + (size_t)row * N_CONV);
        // v[m] -> y[2m] = Re, y[2m+1] = Im.
        orow[t]       = make_float2(v0.x * inv_n, v0.y * inv_n);
        orow[t + 128] = make_float2(v1.x * inv_n, v1.y * inv_n);
        orow[t + 256] = make_float2(v2.x * inv_n, v2.y * inv_n);
        orow[t + 384] = make_float2(v3.x * inv_n, v3.y * inv_n);
    }
}

extern "C" void kernel_launch(void* const* d_in, const int* in_sizes, int n_in,
                              void* d_out, int out_size)
{
    const float* x1 = (const float*)d_in[0];
    const float* x2 = (const float*)d_in[1];
    const float* x3 = (const float*)d_in[2];
    float* out = (float*)d_out;

    mcf_rfft_kernel<<<384, THREADS>>>(x1, x2, x3, out);
}

// round 14
// speedup vs baseline: 1.1203x; 1.0622x over previous
#include <cuda_runtime.h>
#include <cuda_bf16.h>

// Circular self-convolution via half-length real FFT, radix-8.
// One row per CTA: u[m] = x[2m] + i*x[2m+1] -> FFT-512 as THREE radix-8
// stages (L=512,64,8) -> rfft combine + square + inverse-pack (pairwise
// in-place, exclusive ownership) -> exact 3-stage inverse -> de-pack.
// 384 CTAs x 64 threads; each thread owns one full 8-point butterfly.
//
// vs R13 (radix-4, 10 phases): 3 stages halve smem round-trips and index
// math; no twiddle table (per-stage twiddles via 2x MUFU sin/cos.approx +
// power chain; fwd/inv recompute identical values so the unwind is exact).
// Block barriers: 5. Permutation: k=k1+8k2+64k3 -> p=64k1+8k2+k3 (rev8).

#define N_CONV 1024
#define HF 512
#define THREADS 64

#define P2(i) ((i) + ((i) >> 4))

__device__ __forceinline__ int rev8(int k) {
    return ((k & 7) << 6) | (k & 56) | (k >> 6);
}

__device__ __forceinline__ float fsin(float x) {
    float r; asm("sin.approx.f32 %0, %1;" : "=f"(r) : "f"(x)); return r;
}
__device__ __forceinline__ float fcos(float x) {
    float r; asm("cos.approx.f32 %0, %1;" : "=f"(r) : "f"(x)); return r;
}

__device__ __forceinline__ float2 cadd(float2 a, float2 b) { return make_float2(a.x + b.x, a.y + b.y); }
__device__ __forceinline__ float2 csub(float2 a, float2 b) { return make_float2(a.x - b.x, a.y - b.y); }
__device__ __forceinline__ float2 cmul(float2 a, float2 w) {
    return make_float2(a.x * w.x - a.y * w.y, a.x * w.y + a.y * w.x);
}
__device__ __forceinline__ float2 cmulc(float2 a, float2 w) {   // a * conj(w)
    return make_float2(a.x * w.x + a.y * w.y, a.y * w.x - a.x * w.y);
}
__device__ __forceinline__ float2 submuli(float2 a, float2 b) {  // a - i*b
    return make_float2(a.x + b.y, a.y - b.x);
}
__device__ __forceinline__ float2 addmuli(float2 a, float2 b) {  // a + i*b
    return make_float2(a.x - b.y, a.y + b.x);
}
__device__ __forceinline__ float2 csq(float2 a) {
    return make_float2(a.x * a.x - a.y * a.y, 2.0f * a.x * a.y);
}

#define SQH 0.70710678118654752f

// 8-point DFT (negative exponent), in place. Verified on delta input.
__device__ __forceinline__ void dft8(float2* a)
{
    const float2 et0 = cadd(a[0], a[4]), et1 = csub(a[0], a[4]);
    const float2 et2 = cadd(a[2], a[6]), et3 = csub(a[2], a[6]);
    const float2 E0 = cadd(et0, et2), E2 = csub(et0, et2);
    const float2 E1 = submuli(et1, et3), E3 = addmuli(et1, et3);
    const float2 ot0 = cadd(a[1], a[5]), ot1 = csub(a[1], a[5]);
    const float2 ot2 = cadd(a[3], a[7]), ot3 = csub(a[3], a[7]);
    const float2 O0 = cadd(ot0, ot2), O2 = csub(ot0, ot2);
    const float2 O1 = submuli(ot1, ot3), O3 = addmuli(ot1, ot3);
    const float2 G0 = O0;
    const float2 G1 = make_float2(SQH * (O1.x + O1.y), SQH * (O1.y - O1.x)); // *W8
    const float2 G2 = make_float2(O2.y, -O2.x);                              // *W8^2
    const float2 G3 = make_float2(SQH * (O3.y - O3.x), -SQH * (O3.x + O3.y));// *W8^3
    a[0] = cadd(E0, G0);  a[4] = csub(E0, G0);
    a[1] = cadd(E1, G1);  a[5] = csub(E1, G1);
    a[2] = cadd(E2, G2);  a[6] = csub(E2, G2);
    a[3] = cadd(E3, G3);  a[7] = csub(E3, G3);
}

// 8-point IDFT (positive exponent, no 1/8), in place. Verified: idft8(dft8)=8*id.
__device__ __forceinline__ void idft8(float2* a)
{
    const float2 et0 = cadd(a[0], a[4]), et1 = csub(a[0], a[4]);
    const float2 et2 = cadd(a[2], a[6]), et3 = csub(a[2], a[6]);
    const float2 E0 = cadd(et0, et2), E2 = csub(et0, et2);
    const float2 E1 = addmuli(et1, et3), E3 = submuli(et1, et3);
    const float2 ot0 = cadd(a[1], a[5]), ot1 = csub(a[1], a[5]);
    const float2 ot2 = cadd(a[3], a[7]), ot3 = csub(a[3], a[7]);
    const float2 O0 = cadd(ot0, ot2), O2 = csub(ot0, ot2);
    const float2 O1 = addmuli(ot1, ot3), O3 = submuli(ot1, ot3);
    const float2 G0 = O0;
    const float2 G1 = make_float2(SQH * (O1.x - O1.y), SQH * (O1.x + O1.y)); // *W8^-1
    const float2 G2 = make_float2(-O2.y, O2.x);                              // *W8^-2
    const float2 G3 = make_float2(-SQH * (O3.x + O3.y), SQH * (O3.x - O3.y));// *W8^-3
    a[0] = cadd(E0, G0);  a[4] = csub(E0, G0);
    a[1] = cadd(E1, G1);  a[5] = csub(E1, G1);
    a[2] = cadd(E2, G2);  a[6] = csub(E2, G2);
    a[3] = cadd(E3, G3);  a[7] = csub(E3, G3);
}

// Build w^1..w^7 from angle theta (w = e^{-i theta}).
__device__ __forceinline__ void twiddle_chain(float th, float2* w)
{
    w[1] = make_float2(fcos(th), -fsin(th));
    w[2] = cmul(w[1], w[1]);
    w[3] = cmul(w[1], w[2]);
    w[4] = cmul(w[2], w[2]);
    w[5] = cmul(w[1], w[4]);
    w[6] = cmul(w[2], w[4]);
    w[7] = cmul(w[3], w[4]);
}

// Forward radix-8 DIF stage with twiddles (L = 512 or 64).
template<int L>
__device__ __forceinline__ void fwd_stage8(float2* X, int t)
{
    const int q    = L >> 3;
    const int blk  = t / q;
    const int pos  = t % q;
    const int base = blk * L + pos;

    float2 a[8];
    #pragma unroll
    for (int j = 0; j < 8; ++j) a[j] = X[P2(base + j * q)];

    dft8(a);

    float2 w[8];
    twiddle_chain((float)pos * (6.283185307179586f / (float)L), w);
    #pragma unroll
    for (int j = 1; j < 8; ++j) a[j] = cmul(a[j], w[j]);

    #pragma unroll
    for (int j = 0; j < 8; ++j) X[P2(base + j * q)] = a[j];
}

// Last forward stage L=8 (q=1, pos=0 -> no twiddles), thread-local.
__device__ __forceinline__ void fwd_stage8_last(float2* X, int t)
{
    float2 a[8];
    #pragma unroll
    for (int j = 0; j < 8; ++j) a[j] = X[P2(8 * t + j)];
    dft8(a);
    #pragma unroll
    for (int j = 0; j < 8; ++j) X[P2(8 * t + j)] = a[j];
}

// First inverse stage L=8 (no twiddles), thread-local.
__device__ __forceinline__ void inv_stage8_first(float2* X, int t)
{
    float2 a[8];
    #pragma unroll
    for (int j = 0; j < 8; ++j) a[j] = X[P2(8 * t + j)];
    idft8(a);
    #pragma unroll
    for (int j = 0; j < 8; ++j) X[P2(8 * t + j)] = a[j];
}

// Inverse radix-8 stage with un-twiddle (L = 64 here).
template<int L>
__device__ __forceinline__ void inv_stage8(float2* X, int t)
{
    const int q    = L >> 3;
    const int blk  = t / q;
    const int pos  = t % q;
    const int base = blk * L + pos;

    float2 a[8];
    #pragma unroll
    for (int j = 0; j < 8; ++j) a[j] = X[P2(base + j * q)];

    float2 w[8];
    twiddle_chain((float)pos * (6.283185307179586f / (float)L), w);
    #pragma unroll
    for (int j = 1; j < 8; ++j) a[j] = cmulc(a[j], w[j]);

    idft8(a);

    #pragma unroll
    for (int j = 0; j < 8; ++j) X[P2(base + j * q)] = a[j];
}

// Middle unit for pair (k, 512-k): rfft combine + square + inverse-pack.
// Reads/writes ONLY its own two positions (exclusive ownership, in-place).
__device__ __forceinline__ void middle_unit(float2* X, int k)
{
    const int pk = rev8(k);
    const int pm = rev8((HF - k) & (HF - 1));

    const float2 Uk = X[P2(pk)];
    const float2 Um = X[P2(pm)];

    const float2 E = make_float2(0.5f * (Uk.x + Um.x), 0.5f * (Uk.y - Um.y));
    const float2 O = make_float2(0.5f * (Uk.y + Um.y), 0.5f * (Um.x - Uk.x));

    const float th = (float)k * 0.006135923151542565f;    // pi/512
    const float2 w = make_float2(fcos(th), -fsin(th));    // W1024^k

    const float2 wO = cmul(O, w);
    const float2 Xp = cadd(E, wO);             // X[k]
    const float2 Xm = csub(E, wO);             // X[k+512]

    const float2 P = csq(Xp);
    const float2 M = csq(Xm);
    const float2 S  = make_float2(0.5f * (P.x + M.x), 0.5f * (P.y + M.y));
    const float2 Dm = make_float2(0.5f * (P.x - M.x), 0.5f * (P.y - M.y));

    const float2 r = cmulc(Dm, w);             // conj(w)*Dm
    const float2 Vk = make_float2(S.x - r.y, S.y + r.x);        // S + i*r

    const float2 q2 = cmul(make_float2(Dm.x, -Dm.y), w);        // w*conj(Dm)
    const float2 Vm = make_float2(S.x - q2.y, -S.y + q2.x);     // conj(S)+i*q2

    X[P2(pk)] = Vk;
    X[P2(pm)] = Vm;
}

__global__ __launch_bounds__(THREADS, 6)
void mcf_r8_kernel(const float* __restrict__ x1,
                   const float* __restrict__ x2,
                   const float* __restrict__ x3,
                   float* __restrict__ out)
{
    __shared__ __align__(16) float2 X[544];    // 512 + padding

    const int bx  = blockIdx.x;                // 0..383: one row
    const int arr = bx >> 7;
    const int row = bx & 127;

    const float* xp = (arr == 0) ? x1 : ((arr == 1) ? x2 : x3);
    const float* xr = xp + (size_t)row * N_CONV;

    const int t = threadIdx.x;                 // 0..63

    // Prologue: pack u[m] = x[2m] + i*x[2m+1]; thread t owns m = 8t..8t+7.
    {
        const float4* xr4 = (const float4*)xr;
        #pragma unroll
        for (int i = 0; i < 4; ++i) {
            const float4 v = xr4[4 * t + i];
            X[P2(8 * t + 2 * i)]     = make_float2(v.x, v.y);
            X[P2(8 * t + 2 * i + 1)] = make_float2(v.z, v.w);
        }
    }
    __syncthreads();

    // Forward FFT-512: three radix-8 stages.
    fwd_stage8<512>(X, t);  __syncthreads();
    fwd_stage8< 64>(X, t);  __syncwarp();
    fwd_stage8_last(X, t);  __syncthreads();

    // Middle: rfft combine + square + inverse-pack, pairwise in-place.
    #pragma unroll
    for (int u = 0; u < 4; ++u) middle_unit(X, 4 * t + u);
    if (t == 0) middle_unit(X, 256);
    __syncthreads();

    // Inverse: exact unwind.
    inv_stage8_first(X, t); __syncwarp();
    inv_stage8< 64>(X, t);  __syncthreads();

    // Final inverse stage L=512 fused with epilogue de-pack to gmem.
    {
        float2 a[8];
        #pragma unroll
        for (int j = 0; j < 8; ++j) a[j] = X[P2(t + 64 * j)];

        float2 w[8];
        twiddle_chain((float)t * (6.283185307179586f / 512.0f), w);
        #pragma unroll
        for (int j = 1; j < 8; ++j) a[j] = cmulc(a[j], w[j]);

        idft8(a);

        const float inv_n = 1.0f / 512.0f;
        float2* orow = (float2*)(out + (size_t)arr * 128 * N_CONV
                                     + (size_t)row * N_CONV);
        // v[n] at n = t + 64m -> y[2n] = Re, y[2n+1] = Im.
        #pragma unroll
        for (int m = 0; m < 8; ++m)
            orow[t + 64 * m] = make_float2(a[m].x * inv_n, a[m].y * inv_n);
    }
}

extern "C" void kernel_launch(void* const* d_in, const int* in_sizes, int n_in,
                              void* d_out, int out_size)
{
    const float* x1 = (const float*)d_in[0];
    const float* x2 = (const float*)d_in[1];
    const float* x3 = (const float*)d_in[2];
    float* out = (float*)d_out;

    mcf_r8_kernel<<<384, THREADS>>>(x1, x2, x3, out);
}